// round 2
// baseline (speedup 1.0000x reference)
#include <cuda_runtime.h>
#include <cuda_bf16.h>
#include <stdint.h>

// ---------------- problem constants ----------------
#define DIM        512
#define NPAIR      8192
#define TILE       128
#define NTILES     64             // 8192 / 128
#define TILES_PER_CTA 32          // j-tiles per CTA (2 halves of anchor range)
#define NKC        8              // K chunks of 64 bf16 (128 B per row) each
#define BLK_BYTES  16384          // 128 rows x 128 bytes
#define NABUF      4              // anchor-chunk ring depth
#define TOTAL_CHUNKS (TILES_PER_CTA * NKC)   // 256

// ---------------- smem layout (offsets from 1024-aligned base) ----------------
#define SM_P       0
#define SM_AB      (SM_P + NKC * BLK_BYTES)          // 131072
#define SM_RED     (SM_AB + NABUF * BLK_BYTES)       // 196608
#define SM_END     (SM_RED + 128 * 4 * 4)            // 198656
#define SM_DYN     (SM_END + 1024)                   // + alignment slack

// ---------------- device scratch (static: allowed) ----------------
__device__ __nv_bfloat16 g_P[(size_t)NPAIR * DIM];   // normalized positive rows
__device__ __nv_bfloat16 g_A[(size_t)NPAIR * DIM];   // normalized anchor rows
__device__ float g_partial[2 * NPAIR];               // per-half row exp-sums
__device__ float g_diag[NPAIR];                      // cos_ii

// ---------------- PTX helpers (base-ISA only: no tcgen05 on compute_103) ----------------
static __device__ __forceinline__ uint32_t smem_u32(const void* p) {
    uint32_t a;
    asm("{ .reg .u64 t; cvta.to.shared.u64 t, %1; cvt.u32.u64 %0, t; }"
        : "=r"(a) : "l"(p));
    return a;
}

#define CPA16(dst, src) \
    asm volatile("cp.async.cg.shared.global [%0], [%1], 16;" :: "r"(dst), "l"(src))
#define CPA_COMMIT() asm volatile("cp.async.commit_group;" ::: "memory")
#define CPA_WAIT2()  asm volatile("cp.async.wait_group 2;" ::: "memory")

#define LDSM4(r0, r1, r2, r3, addr) \
    asm volatile("ldmatrix.sync.aligned.m8n8.x4.shared.b16 {%0,%1,%2,%3}, [%4];" \
                 : "=r"(r0), "=r"(r1), "=r"(r2), "=r"(r3) : "r"(addr))

static __device__ __forceinline__ void mma16816(float* d, const uint32_t* a,
                                                const uint32_t* b) {
    asm volatile(
        "mma.sync.aligned.m16n8k16.row.col.f32.bf16.bf16.f32 "
        "{%0,%1,%2,%3}, {%4,%5,%6,%7}, {%8,%9}, {%0,%1,%2,%3};"
        : "+f"(d[0]), "+f"(d[1]), "+f"(d[2]), "+f"(d[3])
        : "r"(a[0]), "r"(a[1]), "r"(a[2]), "r"(a[3]), "r"(b[0]), "r"(b[1]));
}

// ---------------- kernel 1: normalize rows, deinterleave, fp32 -> bf16 ----------------
__global__ void __launch_bounds__(256) prep_kernel(const float* __restrict__ x) {
    int warp = blockIdx.x * 8 + (threadIdx.x >> 5);   // = source row in x
    int lid = threadIdx.x & 31;
    const float4* xr = (const float4*)(x + (size_t)warp * DIM);
    float4 v[4];
    float ss = 0.f;
#pragma unroll
    for (int i = 0; i < 4; i++) {
        v[i] = xr[lid + i * 32];
        ss += v[i].x * v[i].x + v[i].y * v[i].y + v[i].z * v[i].z + v[i].w * v[i].w;
    }
#pragma unroll
    for (int o = 16; o; o >>= 1) ss += __shfl_xor_sync(0xffffffffu, ss, o);
    float inv = rsqrtf(ss);   // norms ~sqrt(512): the EPS clamp never binds
    __nv_bfloat16* dst = (warp & 1) ? (g_P + (size_t)(warp >> 1) * DIM)
                                    : (g_A + (size_t)(warp >> 1) * DIM);
#pragma unroll
    for (int i = 0; i < 4; i++) {
        __nv_bfloat162 lo = __floats2bfloat162_rn(v[i].x * inv, v[i].y * inv);
        __nv_bfloat162 hi = __floats2bfloat162_rn(v[i].z * inv, v[i].w * inv);
        uint2 pk;
        pk.x = *(uint32_t*)&lo;
        pk.y = *(uint32_t*)&hi;
        *(uint2*)(dst + (size_t)(lid + i * 32) * 4) = pk;
    }
}

// ---------------- kernel 2: fused cos-GEMM (mma.sync bf16) + exp row-sums ----------------
__global__ void __launch_bounds__(256, 1) angle_main(const float* __restrict__ wp) {
    extern __shared__ char smem_raw[];
    uint32_t sb_raw = smem_u32(smem_raw);
    uint32_t pad = ((sb_raw + 1023u) & ~1023u) - sb_raw;
    char* smem = smem_raw + pad;
    uint32_t sbase = sb_raw + pad;

    const int tid = threadIdx.x, wid = tid >> 5, lid = tid & 31;
    const int wm = wid >> 2, wn = wid & 3;         // 2 x 4 warp grid
    const int it = blockIdx.x >> 1;                // i-tile (positive rows)
    const int half = blockIdx.x & 1;               // anchor half
    const float w = *wp;

    // ldmatrix lane geometry (xor-swizzled 16B chunks within 128B rows)
    const int a_row0 = wm * 64 + (lid & 7) + ((lid >> 3) & 1) * 8;  // + mf*16
    const int a_k = lid >> 4;                                        // k 16B-chunk sel
    const int a_sw = a_row0 & 7;
    const int b_row0 = wn * 32 + (lid & 7) + ((lid >> 4) & 1) * 8;  // + p*16
    const int b_k = (lid >> 3) & 1;
    const int b_sw = b_row0 & 7;

    // ---- resident P tile: 8 swizzled chunks of [128 rows x 128 B] ----
    {
        const char* src = (const char*)(g_P + (size_t)it * TILE * DIM);
        for (int i = tid; i < NKC * 1024; i += 256) {
            int blk = i >> 10, v = i & 1023;
            int row = v >> 3, c = v & 7;
            CPA16(sbase + SM_P + blk * BLK_BYTES + row * 128 + ((c ^ (row & 7)) << 4),
                  src + (size_t)row * (DIM * 2) + blk * 128 + c * 16);
        }
        CPA_COMMIT();
    }

    // issue first 3 anchor chunks
#pragma unroll
    for (int c = 0; c < 3; ++c) {
        int jt = half * TILES_PER_CTA + (c >> 3), kc = c & 7;
        const char* src = (const char*)(g_A + (size_t)jt * TILE * DIM) + kc * 128;
        uint32_t dst = sbase + SM_AB + (c & (NABUF - 1)) * BLK_BYTES;
        for (int u = tid; u < 1024; u += 256) {
            int row = u >> 3, cc = u & 7;
            CPA16(dst + row * 128 + ((cc ^ (row & 7)) << 4),
                  src + (size_t)row * (DIM * 2) + cc * 16);
        }
        CPA_COMMIT();
    }

    float acc[4][4][4];
#pragma unroll
    for (int mf = 0; mf < 4; mf++)
#pragma unroll
        for (int nf = 0; nf < 4; nf++)
#pragma unroll
            for (int k = 0; k < 4; k++) acc[mf][nf][k] = 0.f;
    float rs[8];
#pragma unroll
    for (int r = 0; r < 8; r++) rs[r] = 0.f;

#pragma unroll 1
    for (int c = 0; c < TOTAL_CHUNKS; ++c) {
        CPA_WAIT2();
        __syncthreads();

        // issue chunk c+3 (empty commit keeps group counting aligned)
        {
            int cn = c + 3;
            if (cn < TOTAL_CHUNKS) {
                int jt = half * TILES_PER_CTA + (cn >> 3), kc = cn & 7;
                const char* src = (const char*)(g_A + (size_t)jt * TILE * DIM) + kc * 128;
                uint32_t dst = sbase + SM_AB + (cn & (NABUF - 1)) * BLK_BYTES;
                for (int u = tid; u < 1024; u += 256) {
                    int row = u >> 3, cc = u & 7;
                    CPA16(dst + row * 128 + ((cc ^ (row & 7)) << 4),
                          src + (size_t)row * (DIM * 2) + cc * 16);
                }
            }
            CPA_COMMIT();
        }

        // ---- compute chunk c: 64 k-elems = 4 mma k-steps ----
        const uint32_t pb = sbase + SM_P + (c & 7) * BLK_BYTES;
        const uint32_t bb = sbase + SM_AB + (c & (NABUF - 1)) * BLK_BYTES;
#pragma unroll
        for (int ks = 0; ks < 4; ++ks) {
            uint32_t a[4][4];
#pragma unroll
            for (int mf = 0; mf < 4; ++mf) {
                uint32_t addr = pb + (uint32_t)(a_row0 + mf * 16) * 128 +
                                (uint32_t)(((2 * ks + a_k) ^ a_sw) << 4);
                LDSM4(a[mf][0], a[mf][1], a[mf][2], a[mf][3], addr);
            }
            uint32_t b[4][2];
#pragma unroll
            for (int p = 0; p < 2; ++p) {
                uint32_t addr = bb + (uint32_t)(b_row0 + p * 16) * 128 +
                                (uint32_t)(((2 * ks + b_k) ^ b_sw) << 4);
                uint32_t r0, r1, r2, r3;
                LDSM4(r0, r1, r2, r3, addr);
                b[2 * p][0] = r0; b[2 * p][1] = r1;
                b[2 * p + 1][0] = r2; b[2 * p + 1][1] = r3;
            }
#pragma unroll
            for (int mf = 0; mf < 4; ++mf)
#pragma unroll
                for (int nf = 0; nf < 4; ++nf)
                    mma16816(acc[mf][nf], a[mf], b[nf]);
        }

        // ---- per-j-tile epilogue: exp-accumulate, reset accumulators ----
        if ((c & 7) == 7) {
#pragma unroll
            for (int mf = 0; mf < 4; ++mf)
#pragma unroll
                for (int nf = 0; nf < 4; ++nf) {
                    rs[mf * 2 + 0] += __expf(w * acc[mf][nf][0]) + __expf(w * acc[mf][nf][1]);
                    rs[mf * 2 + 1] += __expf(w * acc[mf][nf][2]) + __expf(w * acc[mf][nf][3]);
#pragma unroll
                    for (int k = 0; k < 4; k++) acc[mf][nf][k] = 0.f;
                }
        }
    }

    // ---- deterministic CTA reduction: lanes (t) -> warps (wn) -> rows ----
#pragma unroll
    for (int r = 0; r < 8; ++r) {
        rs[r] += __shfl_xor_sync(0xffffffffu, rs[r], 1);
        rs[r] += __shfl_xor_sync(0xffffffffu, rs[r], 2);
    }
    float* red = (float*)(smem + SM_RED);
    __syncthreads();   // A-buffer traffic done; red region is fresh
    if ((lid & 3) == 0) {
        int g = lid >> 2;
#pragma unroll
        for (int mf = 0; mf < 4; ++mf) {
            int rl0 = wm * 64 + mf * 16 + g;
            red[(rl0) * 4 + wn] = rs[mf * 2 + 0];
            red[(rl0 + 8) * 4 + wn] = rs[mf * 2 + 1];
        }
    }
    __syncthreads();
    if (tid < 128) {
        float s = red[tid * 4 + 0] + red[tid * 4 + 1] + red[tid * 4 + 2] + red[tid * 4 + 3];
        g_partial[half * NPAIR + it * TILE + tid] = s;
    }
}

// ---------------- kernel 3: diagonal cos_ii (one warp per row) ----------------
__global__ void __launch_bounds__(256) diag_kernel() {
    int row = blockIdx.x * 8 + (threadIdx.x >> 5);
    int lid = threadIdx.x & 31;
    const uint4* p = (const uint4*)(g_P + (size_t)row * DIM);
    const uint4* a = (const uint4*)(g_A + (size_t)row * DIM);
    float s = 0.f;
#pragma unroll
    for (int j = 0; j < 2; ++j) {
        uint4 pv = p[lid + j * 32], av = a[lid + j * 32];
        const uint32_t pw[4] = {pv.x, pv.y, pv.z, pv.w};
        const uint32_t aw[4] = {av.x, av.y, av.z, av.w};
#pragma unroll
        for (int q = 0; q < 4; ++q) {
            __nv_bfloat162 pb = *(const __nv_bfloat162*)&pw[q];
            __nv_bfloat162 ab = *(const __nv_bfloat162*)&aw[q];
            s += __bfloat162float(pb.x) * __bfloat162float(ab.x);
            s += __bfloat162float(pb.y) * __bfloat162float(ab.y);
        }
    }
#pragma unroll
    for (int o = 16; o; o >>= 1) s += __shfl_xor_sync(0xffffffffu, s, o);
    if (lid == 0) g_diag[row] = s;
}

// ---------------- kernel 4: final reduction ----------------
__global__ void __launch_bounds__(256) finalize_kernel(const float* __restrict__ wp,
                                                       float* __restrict__ out) {
    __shared__ float red[256];
    int tid = threadIdx.x;
    float w = *wp;
    float s = 0.f;
    for (int i = tid; i < NPAIR; i += 256) {
        float es = g_partial[i] + g_partial[NPAIR + i];
        s += logf(es) - w * g_diag[i];
    }
    red[tid] = s;
    __syncthreads();
    for (int o = 128; o; o >>= 1) {
        if (tid < o) red[tid] += red[tid + o];
        __syncthreads();
    }
    if (tid == 0) out[0] = red[0] / (float)NPAIR;
}

// ---------------- launch ----------------
extern "C" void kernel_launch(void* const* d_in, const int* in_sizes, int n_in,
                              void* d_out, int out_size) {
    const float* x = (const float*)d_in[0];
    const float* wp = (const float*)d_in[1];
    // b cancels analytically: lse_i - logit_ii is independent of b.

    cudaFuncSetAttribute(angle_main, cudaFuncAttributeMaxDynamicSharedMemorySize, SM_DYN);

    prep_kernel<<<2048, 256>>>(x);
    diag_kernel<<<NPAIR / 8, 256>>>();
    angle_main<<<NTILES * 2, 256, SM_DYN>>>(wp);
    finalize_kernel<<<1, 256>>>(wp, (float*)d_out);
}

// round 3
// speedup vs baseline: 1.0013x; 1.0013x over previous
#include <cuda_runtime.h>
#include <cuda_bf16.h>
#include <stdint.h>

// ---------------- problem constants ----------------
#define DIM        512
#define NPAIR      8192
#define TILE       128
#define NTILES     64             // 8192 / 128
#define TILES_PER_CTA 32          // j-tiles per CTA (2 halves of anchor range)
#define NKC        8              // K chunks of 64 bf16 (128 B per row) each
#define BLK_BYTES  16384          // 128 rows x 128 bytes
#define NABUF      4              // anchor-chunk ring depth
#define TOTAL_CHUNKS (TILES_PER_CTA * NKC)   // 256

// ---------------- smem layout (offsets from 1024-aligned base) ----------------
#define SM_P       0
#define SM_AB      (SM_P + NKC * BLK_BYTES)          // 131072
#define SM_RED     (SM_AB + NABUF * BLK_BYTES)       // 196608
#define SM_END     (SM_RED + 128 * 4 * 4)            // 198656
#define SM_DYN     (SM_END + 1024)                   // + alignment slack

// ---------------- device scratch (static: allowed) ----------------
__device__ __nv_bfloat16 g_P[(size_t)NPAIR * DIM];   // normalized positive rows
__device__ __nv_bfloat16 g_A[(size_t)NPAIR * DIM];   // normalized anchor rows
__device__ float g_partial[2 * NPAIR];               // per-half row exp-sums
__device__ float g_diag[NPAIR];                      // cos_ii

// ---------------- PTX helpers (base-ISA only: no tcgen05 on compute_103) ----------------
static __device__ __forceinline__ uint32_t smem_u32(const void* p) {
    uint32_t a;
    asm("{ .reg .u64 t; cvta.to.shared.u64 t, %1; cvt.u32.u64 %0, t; }"
        : "=r"(a) : "l"(p));
    return a;
}

#define CPA16(dst, src) \
    asm volatile("cp.async.cg.shared.global [%0], [%1], 16;" :: "r"(dst), "l"(src))
#define CPA_COMMIT() asm volatile("cp.async.commit_group;" ::: "memory")
#define CPA_WAIT2()  asm volatile("cp.async.wait_group 2;" ::: "memory")

#define LDSM4(r0, r1, r2, r3, addr) \
    asm volatile("ldmatrix.sync.aligned.m8n8.x4.shared.b16 {%0,%1,%2,%3}, [%4];" \
                 : "=r"(r0), "=r"(r1), "=r"(r2), "=r"(r3) : "r"(addr))

static __device__ __forceinline__ void mma16816(float* d, const uint32_t* a,
                                                const uint32_t* b) {
    asm volatile(
        "mma.sync.aligned.m16n8k16.row.col.f32.bf16.bf16.f32 "
        "{%0,%1,%2,%3}, {%4,%5,%6,%7}, {%8,%9}, {%0,%1,%2,%3};"
        : "+f"(d[0]), "+f"(d[1]), "+f"(d[2]), "+f"(d[3])
        : "r"(a[0]), "r"(a[1]), "r"(a[2]), "r"(a[3]), "r"(b[0]), "r"(b[1]));
}

// ---------------- kernel 1: normalize rows, deinterleave, fp32 -> bf16 ----------------
__global__ void __launch_bounds__(256) prep_kernel(const float* __restrict__ x) {
    int warp = blockIdx.x * 8 + (threadIdx.x >> 5);   // = source row in x
    int lid = threadIdx.x & 31;
    const float4* xr = (const float4*)(x + (size_t)warp * DIM);
    float4 v[4];
    float ss = 0.f;
#pragma unroll
    for (int i = 0; i < 4; i++) {
        v[i] = xr[lid + i * 32];
        ss += v[i].x * v[i].x + v[i].y * v[i].y + v[i].z * v[i].z + v[i].w * v[i].w;
    }
#pragma unroll
    for (int o = 16; o; o >>= 1) ss += __shfl_xor_sync(0xffffffffu, ss, o);
    float inv = rsqrtf(ss);   // norms ~sqrt(512): the EPS clamp never binds
    __nv_bfloat16* dst = (warp & 1) ? (g_P + (size_t)(warp >> 1) * DIM)
                                    : (g_A + (size_t)(warp >> 1) * DIM);
#pragma unroll
    for (int i = 0; i < 4; i++) {
        __nv_bfloat162 lo = __floats2bfloat162_rn(v[i].x * inv, v[i].y * inv);
        __nv_bfloat162 hi = __floats2bfloat162_rn(v[i].z * inv, v[i].w * inv);
        uint2 pk;
        pk.x = *(uint32_t*)&lo;
        pk.y = *(uint32_t*)&hi;
        *(uint2*)(dst + (size_t)(lid + i * 32) * 4) = pk;
    }
}

// ---------------- kernel 2: fused cos-GEMM (mma.sync bf16) + exp row-sums ----------------
__global__ void __launch_bounds__(256, 1) angle_main(const float* __restrict__ wp) {
    extern __shared__ char smem_raw[];
    uint32_t sb_raw = smem_u32(smem_raw);
    uint32_t pad = ((sb_raw + 1023u) & ~1023u) - sb_raw;
    char* smem = smem_raw + pad;
    uint32_t sbase = sb_raw + pad;

    const int tid = threadIdx.x, wid = tid >> 5, lid = tid & 31;
    const int wm = wid >> 2, wn = wid & 3;         // 2 x 4 warp grid
    const int it = blockIdx.x >> 1;                // i-tile (positive rows)
    const int half = blockIdx.x & 1;               // anchor half
    const float w = *wp;

    // ldmatrix lane geometry (xor-swizzled 16B chunks within 128B rows)
    const int a_row0 = wm * 64 + (lid & 7) + ((lid >> 3) & 1) * 8;  // + mf*16
    const int a_k = lid >> 4;                                        // k 16B-chunk sel
    const int a_sw = a_row0 & 7;
    const int b_row0 = wn * 32 + (lid & 7) + ((lid >> 4) & 1) * 8;  // + p*16
    const int b_k = (lid >> 3) & 1;
    const int b_sw = b_row0 & 7;

    // ---- resident P tile: 8 swizzled chunks of [128 rows x 128 B] ----
    {
        const char* src = (const char*)(g_P + (size_t)it * TILE * DIM);
        for (int i = tid; i < NKC * 1024; i += 256) {
            int blk = i >> 10, v = i & 1023;
            int row = v >> 3, c = v & 7;
            CPA16(sbase + SM_P + blk * BLK_BYTES + row * 128 + ((c ^ (row & 7)) << 4),
                  src + (size_t)row * (DIM * 2) + blk * 128 + c * 16);
        }
        CPA_COMMIT();
    }

    // issue first 3 anchor chunks
#pragma unroll
    for (int c = 0; c < 3; ++c) {
        int jt = half * TILES_PER_CTA + (c >> 3), kc = c & 7;
        const char* src = (const char*)(g_A + (size_t)jt * TILE * DIM) + kc * 128;
        uint32_t dst = sbase + SM_AB + (c & (NABUF - 1)) * BLK_BYTES;
        for (int u = tid; u < 1024; u += 256) {
            int row = u >> 3, cc = u & 7;
            CPA16(dst + row * 128 + ((cc ^ (row & 7)) << 4),
                  src + (size_t)row * (DIM * 2) + cc * 16);
        }
        CPA_COMMIT();
    }

    float acc[4][4][4];
#pragma unroll
    for (int mf = 0; mf < 4; mf++)
#pragma unroll
        for (int nf = 0; nf < 4; nf++)
#pragma unroll
            for (int k = 0; k < 4; k++) acc[mf][nf][k] = 0.f;
    float rs[8];
#pragma unroll
    for (int r = 0; r < 8; r++) rs[r] = 0.f;

#pragma unroll 1
    for (int c = 0; c < TOTAL_CHUNKS; ++c) {
        CPA_WAIT2();
        __syncthreads();

        // issue chunk c+3 (empty commit keeps group counting aligned)
        {
            int cn = c + 3;
            if (cn < TOTAL_CHUNKS) {
                int jt = half * TILES_PER_CTA + (cn >> 3), kc = cn & 7;
                const char* src = (const char*)(g_A + (size_t)jt * TILE * DIM) + kc * 128;
                uint32_t dst = sbase + SM_AB + (cn & (NABUF - 1)) * BLK_BYTES;
                for (int u = tid; u < 1024; u += 256) {
                    int row = u >> 3, cc = u & 7;
                    CPA16(dst + row * 128 + ((cc ^ (row & 7)) << 4),
                          src + (size_t)row * (DIM * 2) + cc * 16);
                }
            }
            CPA_COMMIT();
        }

        // ---- compute chunk c: 64 k-elems = 4 mma k-steps ----
        const uint32_t pb = sbase + SM_P + (c & 7) * BLK_BYTES;
        const uint32_t bb = sbase + SM_AB + (c & (NABUF - 1)) * BLK_BYTES;
#pragma unroll
        for (int ks = 0; ks < 4; ++ks) {
            uint32_t a[4][4];
#pragma unroll
            for (int mf = 0; mf < 4; ++mf) {
                uint32_t addr = pb + (uint32_t)(a_row0 + mf * 16) * 128 +
                                (uint32_t)(((2 * ks + a_k) ^ a_sw) << 4);
                LDSM4(a[mf][0], a[mf][1], a[mf][2], a[mf][3], addr);
            }
            uint32_t b[4][2];
#pragma unroll
            for (int p = 0; p < 2; ++p) {
                uint32_t addr = bb + (uint32_t)(b_row0 + p * 16) * 128 +
                                (uint32_t)(((2 * ks + b_k) ^ b_sw) << 4);
                uint32_t r0, r1, r2, r3;
                LDSM4(r0, r1, r2, r3, addr);
                b[2 * p][0] = r0; b[2 * p][1] = r1;
                b[2 * p + 1][0] = r2; b[2 * p + 1][1] = r3;
            }
#pragma unroll
            for (int mf = 0; mf < 4; ++mf)
#pragma unroll
                for (int nf = 0; nf < 4; ++nf)
                    mma16816(acc[mf][nf], a[mf], b[nf]);
        }

        // ---- per-j-tile epilogue: exp-accumulate, reset accumulators ----
        if ((c & 7) == 7) {
#pragma unroll
            for (int mf = 0; mf < 4; ++mf)
#pragma unroll
                for (int nf = 0; nf < 4; ++nf) {
                    rs[mf * 2 + 0] += __expf(w * acc[mf][nf][0]) + __expf(w * acc[mf][nf][1]);
                    rs[mf * 2 + 1] += __expf(w * acc[mf][nf][2]) + __expf(w * acc[mf][nf][3]);
#pragma unroll
                    for (int k = 0; k < 4; k++) acc[mf][nf][k] = 0.f;
                }
        }
    }

    // ---- deterministic CTA reduction: lanes (t) -> warps (wn) -> rows ----
#pragma unroll
    for (int r = 0; r < 8; ++r) {
        rs[r] += __shfl_xor_sync(0xffffffffu, rs[r], 1);
        rs[r] += __shfl_xor_sync(0xffffffffu, rs[r], 2);
    }
    float* red = (float*)(smem + SM_RED);
    __syncthreads();   // A-buffer traffic done; red region is fresh
    if ((lid & 3) == 0) {
        int g = lid >> 2;
#pragma unroll
        for (int mf = 0; mf < 4; ++mf) {
            int rl0 = wm * 64 + mf * 16 + g;
            red[(rl0) * 4 + wn] = rs[mf * 2 + 0];
            red[(rl0 + 8) * 4 + wn] = rs[mf * 2 + 1];
        }
    }
    __syncthreads();
    if (tid < 128) {
        float s = red[tid * 4 + 0] + red[tid * 4 + 1] + red[tid * 4 + 2] + red[tid * 4 + 3];
        g_partial[half * NPAIR + it * TILE + tid] = s;
    }
}

// ---------------- kernel 3: diagonal cos_ii (one warp per row) ----------------
__global__ void __launch_bounds__(256) diag_kernel() {
    int row = blockIdx.x * 8 + (threadIdx.x >> 5);
    int lid = threadIdx.x & 31;
    const uint4* p = (const uint4*)(g_P + (size_t)row * DIM);
    const uint4* a = (const uint4*)(g_A + (size_t)row * DIM);
    float s = 0.f;
#pragma unroll
    for (int j = 0; j < 2; ++j) {
        uint4 pv = p[lid + j * 32], av = a[lid + j * 32];
        const uint32_t pw[4] = {pv.x, pv.y, pv.z, pv.w};
        const uint32_t aw[4] = {av.x, av.y, av.z, av.w};
#pragma unroll
        for (int q = 0; q < 4; ++q) {
            __nv_bfloat162 pb = *(const __nv_bfloat162*)&pw[q];
            __nv_bfloat162 ab = *(const __nv_bfloat162*)&aw[q];
            s += __bfloat162float(pb.x) * __bfloat162float(ab.x);
            s += __bfloat162float(pb.y) * __bfloat162float(ab.y);
        }
    }
#pragma unroll
    for (int o = 16; o; o >>= 1) s += __shfl_xor_sync(0xffffffffu, s, o);
    if (lid == 0) g_diag[row] = s;
}

// ---------------- kernel 4: final reduction ----------------
__global__ void __launch_bounds__(256) finalize_kernel(const float* __restrict__ wp,
                                                       float* __restrict__ out) {
    __shared__ float red[256];
    int tid = threadIdx.x;
    float w = *wp;
    float s = 0.f;
    for (int i = tid; i < NPAIR; i += 256) {
        float es = g_partial[i] + g_partial[NPAIR + i];
        s += logf(es) - w * g_diag[i];
    }
    red[tid] = s;
    __syncthreads();
    for (int o = 128; o; o >>= 1) {
        if (tid < o) red[tid] += red[tid + o];
        __syncthreads();
    }
    if (tid == 0) out[0] = red[0] / (float)NPAIR;
}

// ---------------- launch ----------------
extern "C" void kernel_launch(void* const* d_in, const int* in_sizes, int n_in,
                              void* d_out, int out_size) {
    const float* x = (const float*)d_in[0];
    const float* wp = (const float*)d_in[1];
    // b cancels analytically: lse_i - logit_ii is independent of b.

    cudaFuncSetAttribute(angle_main, cudaFuncAttributeMaxDynamicSharedMemorySize, SM_DYN);

    prep_kernel<<<2048, 256>>>(x);
    diag_kernel<<<NPAIR / 8, 256>>>();
    angle_main<<<NTILES * 2, 256, SM_DYN>>>(wp);
    finalize_kernel<<<1, 256>>>(wp, (float*)d_out);
}